// round 5
// baseline (speedup 1.0000x reference)
#include <cuda_runtime.h>
#include <stdint.h>

#define CC   128
#define CI   32
#define HH   128
#define WW   256
#define BB   8
#define HW   (HH*WW)

#define TW   32
#define TH   16
#define HTW  (TW + 2)   // 34
#define HTH  (TH + 2)   // 18

// Precomputed parameters (filled by prep kernel each launch; deterministic).
__device__ uint32_t g_w1m[CI][4];
__device__ float    g_inv1[CI], g_bb1[CI];
__device__ uint32_t g_w2m[CI][9];
__device__ float    g_inv2[CI], g_bb2[CI];
__device__ uint32_t g_w3m[CC];
__device__ float    g_inv3[CC], g_bb3[CC];

// ---------------------------------------------------------------------------
// Prep (parallel): binarize weights into bitmasks via warp ballot, fold BN.
// bit c = (w > 0);  bn(z) = z*inv + bb, inv = g/sqrt(v+eps) > 0, bb = b - m*inv
// ---------------------------------------------------------------------------
__global__ void __launch_bounds__(256) prep_kernel(
    const float* __restrict__ w1, const float* __restrict__ g1,
    const float* __restrict__ b1, const float* __restrict__ m1, const float* __restrict__ v1,
    const float* __restrict__ w2, const float* __restrict__ g2,
    const float* __restrict__ b2, const float* __restrict__ m2, const float* __restrict__ v2,
    const float* __restrict__ w3, const float* __restrict__ g3,
    const float* __restrict__ b3, const float* __restrict__ m3, const float* __restrict__ v3)
{
    int tid  = threadIdx.x;
    int warp = tid >> 5;
    int lane = tid & 31;

    if (blockIdx.x == 0) {
        for (int word = warp; word < CI * 4; word += 8) {
            int oc = word >> 2, j = word & 3;
            uint32_t m = __ballot_sync(0xffffffffu, w1[oc * CC + j * 32 + lane] > 0.f);
            if (lane == 0) g_w1m[oc][j] = m;
        }
        if (tid < CI) {
            float inv = __fdiv_rn(g1[tid], __fsqrt_rn(__fadd_rn(v1[tid], 1e-5f)));
            g_inv1[tid] = inv;
            g_bb1[tid]  = __fadd_rn(b1[tid], -__fmul_rn(m1[tid], inv));
        }
    } else if (blockIdx.x == 1) {
        for (int word = warp; word < CI * 9; word += 8) {
            int oc = word / 9, t9 = word - oc * 9;
            uint32_t m = __ballot_sync(0xffffffffu, w2[oc * (CI * 9) + lane * 9 + t9] > 0.f);
            if (lane == 0) g_w2m[oc][t9] = m;
        }
        if (tid < CI) {
            float inv = __fdiv_rn(g2[tid], __fsqrt_rn(__fadd_rn(v2[tid], 1e-5f)));
            g_inv2[tid] = inv;
            g_bb2[tid]  = __fadd_rn(b2[tid], -__fmul_rn(m2[tid], inv));
        }
    } else {
        for (int word = warp; word < CC; word += 8) {
            uint32_t m = __ballot_sync(0xffffffffu, w3[word * CI + lane] > 0.f);
            if (lane == 0) g_w3m[word] = m;
        }
        if (tid < CC) {
            float inv = __fdiv_rn(g3[tid], __fsqrt_rn(__fadd_rn(v3[tid], 1e-5f)));
            g_inv3[tid] = inv;
            g_bb3[tid]  = __fadd_rn(b3[tid], -__fmul_rn(m3[tid], inv));
        }
    }
}

// ---------------------------------------------------------------------------
// Fused kernel: per 32x16 tile,
//   phase 1: conv1 (1x1, 128->32) + bn + sign over tile+halo -> sh1 bitmasks
//            (x read from DRAM once; halo recomputed redundantly per block)
//   phase 2: conv2 (3x3, zero-pad AFTER binarize -> per-tap validity at border)
//   phase 3: conv3 (1x1, 32->128) + bn + prelu + residual (x re-read = L2 hit)
//            + prelu, streaming store.
// 256 threads, 2 pixels/thread in phases 2-3.
// ---------------------------------------------------------------------------
__global__ void __launch_bounds__(256) k_fused(
    const float* __restrict__ x, float* __restrict__ out,
    const float* __restrict__ a3p, const float* __restrict__ aoutp)
{
    __shared__ uint32_t sh1[HTH][HTW];
    __shared__ uint32_t sw1[CI][4];
    __shared__ float sinv1[CI], sbb1[CI];
    __shared__ uint32_t sw2[CI][9];
    __shared__ float sinv2[CI], sbb2[CI];
    __shared__ uint32_t sw3[CC];
    __shared__ float sinv3[CC], sbb3[CC];

    int tid = threadIdx.x;
    int tx  = tid & (TW - 1);
    int ty  = tid / TW;            // 0..7
    int w0  = blockIdx.x * TW;
    int h0  = blockIdx.y * TH;
    int b   = blockIdx.z;

    if (tid < CC) { sw3[tid] = g_w3m[tid]; sinv3[tid] = g_inv3[tid]; sbb3[tid] = g_bb3[tid]; }
    if (tid < CI) {
        sinv1[tid] = g_inv1[tid]; sbb1[tid] = g_bb1[tid];
        sinv2[tid] = g_inv2[tid]; sbb2[tid] = g_bb2[tid];
        #pragma unroll
        for (int j = 0; j < 4; j++) sw1[tid][j] = g_w1m[tid][j];
        #pragma unroll
        for (int t9 = 0; t9 < 9; t9++) sw2[tid][t9] = g_w2m[tid][t9];
    }
    __syncthreads();

    const float* xb = x + (size_t)b * (CC * HW);

    // ---- Phase 1: conv1+bn+sign over the (TH+2)x(TW+2) halo region ----
    for (int it = tid; it < HTH * HTW; it += 256) {
        int hy = it / HTW, hx = it - hy * HTW;
        int gh = h0 + hy - 1, gw = w0 + hx - 1;
        uint32_t outm = 0;
        if (gh >= 0 && gh < HH && gw >= 0 && gw < WW) {
            const float* xp = xb + (size_t)gh * WW + gw;
            uint32_t s0 = 0, s1 = 0, s2 = 0, s3 = 0;
            #pragma unroll
            for (int i = 0; i < 32; i++) {
                if (xp[(i      ) * HW] > 0.f) s0 |= (1u << i);
                if (xp[(i +  32) * HW] > 0.f) s1 |= (1u << i);
                if (xp[(i +  64) * HW] > 0.f) s2 |= (1u << i);
                if (xp[(i +  96) * HW] > 0.f) s3 |= (1u << i);
            }
            #pragma unroll
            for (int oc = 0; oc < CI; oc++) {
                int pc = __popc(s0 ^ sw1[oc][0]) + __popc(s1 ^ sw1[oc][1])
                       + __popc(s2 ^ sw1[oc][2]) + __popc(s3 ^ sw1[oc][3]);
                float v = __fadd_rn(__fmul_rn((float)(128 - 2 * pc), sinv1[oc]), sbb1[oc]);
                if (v > 0.f) outm |= (1u << oc);
            }
        }
        sh1[hy][hx] = outm;
    }
    __syncthreads();

    // ---- Phase 2: conv2+bn+sign for 2 pixels/thread ----
    // Pixel p0 at (ty, tx), p1 at (ty+8, tx). Center of p is sh1[tyP+1][tx+1];
    // tap t offset (t/3-1, t%3-1) -> gather sh1[tyP + t/3][tx + t%3].
    const bool border = (w0 == 0) | (h0 == 0) | (w0 + TW == WW) | (h0 + TH == HH);
    int gh0 = h0 + ty, gh1 = h0 + ty + 8, gw = w0 + tx;

    uint32_t n0[9], n1[9];
    #pragma unroll
    for (int t = 0; t < 9; t++) {
        n0[t] = sh1[ty     + t / 3][tx + t % 3];
        n1[t] = sh1[ty + 8 + t / 3][tx + t % 3];
    }

    uint32_t h2b0 = 0, h2b1 = 0;
    if (!border) {
        #pragma unroll
        for (int oc = 0; oc < CI; oc++) {
            int p0 = 0, p1 = 0;
            #pragma unroll
            for (int t = 0; t < 9; t++) {
                p0 += __popc(n0[t] ^ sw2[oc][t]);
                p1 += __popc(n1[t] ^ sw2[oc][t]);
            }
            float v0 = __fadd_rn(__fmul_rn((float)(288 - 2 * p0), sinv2[oc]), sbb2[oc]);
            float v1 = __fadd_rn(__fmul_rn((float)(288 - 2 * p1), sinv2[oc]), sbb2[oc]);
            if (v0 > 0.f) h2b0 |= (1u << oc);
            if (v1 > 0.f) h2b1 |= (1u << oc);
        }
    } else {
        bool ok0[9], ok1[9];
        #pragma unroll
        for (int t = 0; t < 9; t++) {
            int dy = t / 3 - 1, dx = t % 3 - 1;
            int xx = gw + dx;
            bool okx = (xx >= 0) & (xx < WW);
            int y0 = gh0 + dy, y1 = gh1 + dy;
            ok0[t] = okx & (y0 >= 0) & (y0 < HH);
            ok1[t] = okx & (y1 >= 0) & (y1 < HH);
        }
        #pragma unroll
        for (int oc = 0; oc < CI; oc++) {
            int z0 = 0, z1 = 0;
            #pragma unroll
            for (int t = 0; t < 9; t++) {
                int c0 = 32 - 2 * __popc(n0[t] ^ sw2[oc][t]);
                int c1 = 32 - 2 * __popc(n1[t] ^ sw2[oc][t]);
                z0 += ok0[t] ? c0 : 0;
                z1 += ok1[t] ? c1 : 0;
            }
            float v0 = __fadd_rn(__fmul_rn((float)z0, sinv2[oc]), sbb2[oc]);
            float v1 = __fadd_rn(__fmul_rn((float)z1, sinv2[oc]), sbb2[oc]);
            if (v0 > 0.f) h2b0 |= (1u << oc);
            if (v1 > 0.f) h2b1 |= (1u << oc);
        }
    }

    // ---- Phase 3: conv3 + bn + prelu + residual + prelu ----
    float a3   = a3p[0];
    float aout = aoutp[0];
    size_t base0 = (size_t)b * (CC * HW) + (size_t)gh0 * WW + gw;
    size_t base1 = base0 + (size_t)8 * WW;
    const float* xp0 = x + base0;
    const float* xp1 = x + base1;
    float* op0 = out + base0;
    float* op1 = out + base1;

    #pragma unroll 8
    for (int c = 0; c < CC; c++) {
        int z0 = 32 - 2 * __popc(h2b0 ^ sw3[c]);
        int z1 = 32 - 2 * __popc(h2b1 ^ sw3[c]);
        float v0 = __fadd_rn(__fmul_rn((float)z0, sinv3[c]), sbb3[c]);
        float v1 = __fadd_rn(__fmul_rn((float)z1, sinv3[c]), sbb3[c]);
        v0 = (v0 >= 0.f) ? v0 : a3 * v0;
        v1 = (v1 >= 0.f) ? v1 : a3 * v1;
        float s0 = v0 + xp0[(size_t)c * HW];
        float s1 = v1 + xp1[(size_t)c * HW];
        s0 = (s0 >= 0.f) ? s0 : aout * s0;
        s1 = (s1 >= 0.f) ? s1 : aout * s1;
        __stwt(op0 + (size_t)c * HW, s0);
        __stwt(op1 + (size_t)c * HW, s1);
    }
}

// ---------------------------------------------------------------------------
extern "C" void kernel_launch(void* const* d_in, const int* in_sizes, int n_in,
                              void* d_out, int out_size)
{
    const float* x  = (const float*)d_in[0];
    const float* w1 = (const float*)d_in[1];
    const float* g1 = (const float*)d_in[2];
    const float* b1 = (const float*)d_in[3];
    const float* m1 = (const float*)d_in[4];
    const float* v1 = (const float*)d_in[5];
    // d_in[6] = a1 (unused: prelu with a>0 never changes the following sign)
    const float* w2 = (const float*)d_in[7];
    const float* g2 = (const float*)d_in[8];
    const float* b2 = (const float*)d_in[9];
    const float* m2 = (const float*)d_in[10];
    const float* v2 = (const float*)d_in[11];
    // d_in[12] = a2 (unused, same reason)
    const float* w3 = (const float*)d_in[13];
    const float* g3 = (const float*)d_in[14];
    const float* b3 = (const float*)d_in[15];
    const float* m3 = (const float*)d_in[16];
    const float* v3 = (const float*)d_in[17];
    const float* a3 = (const float*)d_in[18];
    const float* ao = (const float*)d_in[19];
    float* out = (float*)d_out;

    prep_kernel<<<3, 256>>>(w1, g1, b1, m1, v1,
                            w2, g2, b2, m2, v2,
                            w3, g3, b3, m3, v3);

    dim3 grid(WW / TW, HH / TH, BB);   // 8 x 8 x 8 = 512 blocks
    k_fused<<<grid, 256>>>(x, out, a3, ao);
}

// round 6
// speedup vs baseline: 1.7329x; 1.7329x over previous
#include <cuda_runtime.h>
#include <stdint.h>

#define CC   128
#define CI   32
#define HH   128
#define WW   256
#define BB   8
#define HW   (HH*WW)

// Precomputed parameters (filled by prep kernel each launch; deterministic).
__device__ uint32_t g_w1m[CI][4];
__device__ float    g_inv1[CI], g_bb1[CI];
__device__ uint32_t g_w2m[CI][9];
__device__ float    g_inv2[CI], g_bb2[CI];
__device__ uint32_t g_w3m[CC];
__device__ float    g_inv3[CC], g_bb3[CC];

// Scratch: h1 binarized activations, 32 channels packed per pixel. 1 MB.
__device__ uint32_t g_h1b[BB * HW];

// ---------------------------------------------------------------------------
// Prep (parallel): binarize weights into bitmasks via warp ballot, fold BN.
// bit c = (w > 0);  bn(z) = z*inv + bb, inv = g/sqrt(v+eps) > 0, bb = b - m*inv
// ---------------------------------------------------------------------------
__global__ void __launch_bounds__(256) prep_kernel(
    const float* __restrict__ w1, const float* __restrict__ g1,
    const float* __restrict__ b1, const float* __restrict__ m1, const float* __restrict__ v1,
    const float* __restrict__ w2, const float* __restrict__ g2,
    const float* __restrict__ b2, const float* __restrict__ m2, const float* __restrict__ v2,
    const float* __restrict__ w3, const float* __restrict__ g3,
    const float* __restrict__ b3, const float* __restrict__ m3, const float* __restrict__ v3)
{
    int tid  = threadIdx.x;
    int warp = tid >> 5;
    int lane = tid & 31;

    if (blockIdx.x == 0) {
        // w1: [CI][CC] 1x1 -> 128 mask words (oc, j)
        for (int word = warp; word < CI * 4; word += 8) {
            int oc = word >> 2, j = word & 3;
            uint32_t m = __ballot_sync(0xffffffffu, w1[oc * CC + j * 32 + lane] > 0.f);
            if (lane == 0) g_w1m[oc][j] = m;
        }
        if (tid < CI) {
            float inv = __fdiv_rn(g1[tid], __fsqrt_rn(__fadd_rn(v1[tid], 1e-5f)));
            g_inv1[tid] = inv;
            g_bb1[tid]  = __fadd_rn(b1[tid], -__fmul_rn(m1[tid], inv));
        }
    } else if (blockIdx.x == 1) {
        // w2: [CI][CI][3][3] -> 288 mask words (oc, t9), lane = input channel
        for (int word = warp; word < CI * 9; word += 8) {
            int oc = word / 9, t9 = word - oc * 9;
            uint32_t m = __ballot_sync(0xffffffffu, w2[oc * (CI * 9) + lane * 9 + t9] > 0.f);
            if (lane == 0) g_w2m[oc][t9] = m;
        }
        if (tid < CI) {
            float inv = __fdiv_rn(g2[tid], __fsqrt_rn(__fadd_rn(v2[tid], 1e-5f)));
            g_inv2[tid] = inv;
            g_bb2[tid]  = __fadd_rn(b2[tid], -__fmul_rn(m2[tid], inv));
        }
    } else {
        // w3: [CC][CI] 1x1 -> 128 mask words
        for (int word = warp; word < CC; word += 8) {
            uint32_t m = __ballot_sync(0xffffffffu, w3[word * CI + lane] > 0.f);
            if (lane == 0) g_w3m[word] = m;
        }
        if (tid < CC) {
            float inv = __fdiv_rn(g3[tid], __fsqrt_rn(__fadd_rn(v3[tid], 1e-5f)));
            g_inv3[tid] = inv;
            g_bb3[tid]  = __fadd_rn(b3[tid], -__fmul_rn(m3[tid], inv));
        }
    }
}

// ---------------------------------------------------------------------------
// Kernel A: conv1 (1x1, 128->32) + bn + sign -> packed h1 bitmask per pixel.
// Full grid: 1024 blocks (all 8 batches).
// ---------------------------------------------------------------------------
__global__ void __launch_bounds__(256) k_conv1(const float* __restrict__ x)
{
    __shared__ uint32_t sw1[CI][4];
    __shared__ float sinv1[CI], sbb1[CI];
    int tid = threadIdx.x;
    if (tid < CI) {
        sinv1[tid] = g_inv1[tid]; sbb1[tid] = g_bb1[tid];
        #pragma unroll
        for (int j = 0; j < 4; j++) sw1[tid][j] = g_w1m[tid][j];
    }
    __syncthreads();

    int px = blockIdx.x * 256 + tid;     // 0 .. B*H*W-1 (exact multiple)
    int b  = px / HW;
    int p  = px - b * HW;
    const float* xp = x + (size_t)b * (CC * HW) + p;

    uint32_t s0 = 0, s1 = 0, s2 = 0, s3 = 0;
    #pragma unroll
    for (int i = 0; i < 32; i++) {
        if (xp[(i      ) * HW] > 0.f) s0 |= (1u << i);
        if (xp[(i +  32) * HW] > 0.f) s1 |= (1u << i);
        if (xp[(i +  64) * HW] > 0.f) s2 |= (1u << i);
        if (xp[(i +  96) * HW] > 0.f) s3 |= (1u << i);
    }

    uint32_t outm = 0;
    #pragma unroll
    for (int oc = 0; oc < CI; oc++) {
        int pc = __popc(s0 ^ sw1[oc][0]) + __popc(s1 ^ sw1[oc][1])
               + __popc(s2 ^ sw1[oc][2]) + __popc(s3 ^ sw1[oc][3]);
        float z = (float)(128 - 2 * pc);
        float v = __fadd_rn(__fmul_rn(z, sinv1[oc]), sbb1[oc]);
        if (v > 0.f) outm |= (1u << oc);
    }
    g_h1b[px] = outm;
}

// ---------------------------------------------------------------------------
// Kernel B: conv2 (3x3, zero-pad AFTER binarize) + conv3 (1x1, 32->128)
//           + bn + prelu + residual + prelu. Tile 32(W) x 8(H), 1 px/thread.
// ---------------------------------------------------------------------------
#define TW 32
#define TH 8

__global__ void __launch_bounds__(256) k_main(
    const float* __restrict__ x, float* __restrict__ out,
    const float* __restrict__ a3p, const float* __restrict__ aoutp)
{
    __shared__ uint32_t sh1[TH + 2][TW + 2];
    __shared__ uint32_t sw2[CI][9];
    __shared__ float sinv2[CI], sbb2[CI];
    __shared__ uint32_t sw3[CC];
    __shared__ float sinv3[CC], sbb3[CC];

    int tid = threadIdx.x;
    int tx = tid & (TW - 1);
    int ty = tid / TW;
    int w0 = blockIdx.x * TW;
    int h0 = blockIdx.y * TH;
    int b  = blockIdx.z;

    if (tid < CC) { sw3[tid] = g_w3m[tid]; sinv3[tid] = g_inv3[tid]; sbb3[tid] = g_bb3[tid]; }
    if (tid < CI) {
        sinv2[tid] = g_inv2[tid]; sbb2[tid] = g_bb2[tid];
        #pragma unroll
        for (int t9 = 0; t9 < 9; t9++) sw2[tid][t9] = g_w2m[tid][t9];
    }

    const bool border = (w0 == 0) | (h0 == 0) | (w0 + TW == WW) | (h0 + TH == HH);

    // Load h1 bitmask tile + 1-pixel halo
    const uint32_t* h1b = g_h1b + (size_t)b * HW;
    for (int it = tid; it < (TH + 2) * (TW + 2); it += 256) {
        int hy = it / (TW + 2), hx = it - hy * (TW + 2);
        int gh = h0 + hy - 1, gw = w0 + hx - 1;
        uint32_t v = 0;
        if (gh >= 0 && gh < HH && gw >= 0 && gw < WW) v = h1b[gh * WW + gw];
        sh1[hy][hx] = v;
    }
    __syncthreads();

    int gh = h0 + ty, gw = w0 + tx;

    // conv2 neighborhood masks: center at sh1[ty+1][tx+1]; tap t offset
    // (t/3-1, t%3-1) -> gather sh1[ty + t/3][tx + t%3].
    uint32_t n[9];
    #pragma unroll
    for (int t = 0; t < 9; t++)
        n[t] = sh1[ty + t / 3][tx + t % 3];

    uint32_t h2b = 0;
    if (!border) {
        // Interior: all 9 taps valid -> z = 288 - 2 * sum(popc)
        #pragma unroll
        for (int oc = 0; oc < CI; oc++) {
            int pc = 0;
            #pragma unroll
            for (int t = 0; t < 9; t++) pc += __popc(n[t] ^ sw2[oc][t]);
            float v = __fadd_rn(__fmul_rn((float)(288 - 2 * pc), sinv2[oc]), sbb2[oc]);
            if (v > 0.f) h2b |= (1u << oc);
        }
    } else {
        bool ok[9];
        #pragma unroll
        for (int t = 0; t < 9; t++) {
            int yy = gh + t / 3 - 1, xx = gw + t % 3 - 1;
            ok[t] = (yy >= 0) & (yy < HH) & (xx >= 0) & (xx < WW);
        }
        #pragma unroll
        for (int oc = 0; oc < CI; oc++) {
            int z = 0;
            #pragma unroll
            for (int t = 0; t < 9; t++) {
                int c9 = 32 - 2 * __popc(n[t] ^ sw2[oc][t]);
                z += ok[t] ? c9 : 0;
            }
            float v = __fadd_rn(__fmul_rn((float)z, sinv2[oc]), sbb2[oc]);
            if (v > 0.f) h2b |= (1u << oc);
        }
    }

    // conv3 + bn + prelu + residual + prelu
    float a3   = a3p[0];
    float aout = aoutp[0];
    size_t base = (size_t)b * (CC * HW) + (size_t)gh * WW + gw;
    const float* xp = x + base;
    float* op = out + base;

    #pragma unroll 16
    for (int c = 0; c < CC; c++) {
        int z = 32 - 2 * __popc(h2b ^ sw3[c]);
        float v = __fadd_rn(__fmul_rn((float)z, sinv3[c]), sbb3[c]);
        v = (v >= 0.f) ? v : a3 * v;
        float s = v + xp[(size_t)c * HW];
        s = (s >= 0.f) ? s : aout * s;
        __stwt(op + (size_t)c * HW, s);
    }
}

// ---------------------------------------------------------------------------
extern "C" void kernel_launch(void* const* d_in, const int* in_sizes, int n_in,
                              void* d_out, int out_size)
{
    const float* x  = (const float*)d_in[0];
    const float* w1 = (const float*)d_in[1];
    const float* g1 = (const float*)d_in[2];
    const float* b1 = (const float*)d_in[3];
    const float* m1 = (const float*)d_in[4];
    const float* v1 = (const float*)d_in[5];
    // d_in[6] = a1 (unused: prelu with a>0 never changes the following sign)
    const float* w2 = (const float*)d_in[7];
    const float* g2 = (const float*)d_in[8];
    const float* b2 = (const float*)d_in[9];
    const float* m2 = (const float*)d_in[10];
    const float* v2 = (const float*)d_in[11];
    // d_in[12] = a2 (unused, same reason)
    const float* w3 = (const float*)d_in[13];
    const float* g3 = (const float*)d_in[14];
    const float* b3 = (const float*)d_in[15];
    const float* m3 = (const float*)d_in[16];
    const float* v3 = (const float*)d_in[17];
    const float* a3 = (const float*)d_in[18];
    const float* ao = (const float*)d_in[19];
    float* out = (float*)d_out;

    prep_kernel<<<3, 256>>>(w1, g1, b1, m1, v1,
                            w2, g2, b2, m2, v2,
                            w3, g3, b3, m3, v3);

    // Full grids: 1024 blocks each (~7 blocks/SM) — bandwidth-bound, not
    // latency-bound (R4 lesson), no register blowup (R5 lesson).
    k_conv1<<<(BB * HW) / 256, 256>>>(x);

    dim3 grid(WW / TW, HH / TH, BB);   // 8 x 16 x 8 = 1024 blocks
    k_main<<<grid, 256>>>(x, out, a3, ao);
}